// round 12
// baseline (speedup 1.0000x reference)
#include <cuda_runtime.h>
#include <cstdint>

#define B_ 4
#define N_ 8192
#define F_ 64

// ---- scratch (__device__ globals; allocation-free rule) ----
__device__ float g_yt[256 * N_];      // (Z@W)^T tf32-rounded, [n=b*64+f][k], 8 MB
__device__ float g_z[B_ * N_ * F_];   // layer-1 activations, 8 MB
__device__ float g_part[2 * N_ * 256];// split-K partials, 16 MB

// =================== helpers ===================
__device__ __forceinline__ uint32_t s2u(const void* p) {
    uint32_t a;
    asm("{ .reg .u64 t; cvta.to.shared.u64 t, %1; cvt.u32.u64 %0, t; }" : "=r"(a) : "l"(p));
    return a;
}
__device__ __forceinline__ uint32_t tf32r(float x) {  // round-to-nearest tf32 (sm_80+)
    uint32_t u;
    asm("cvt.rna.tf32.f32 %0, %1;" : "=r"(u) : "f"(x));
    return u;
}
__device__ __forceinline__ uint32_t tf32ru(uint32_t x) {
    uint32_t u;
    asm("cvt.rna.tf32.f32 %0, %1;" : "=r"(u) : "f"(__uint_as_float(x)));
    return u;
}

#define MMA_TF32(d, a, b) \
    asm volatile( \
        "mma.sync.aligned.m16n8k8.row.col.f32.tf32.tf32.f32 " \
        "{%0,%1,%2,%3}, {%4,%5,%6,%7}, {%8,%9}, {%0,%1,%2,%3};" \
        : "+f"((d)[0]), "+f"((d)[1]), "+f"((d)[2]), "+f"((d)[3]) \
        : "r"((a)[0]), "r"((a)[1]), "r"((a)[2]), "r"((a)[3]), \
          "r"((b)[0]), "r"((b)[1]))

#define LDMX4(d, addr) \
    asm volatile("ldmatrix.sync.aligned.m8n8.x4.shared.b16 {%0,%1,%2,%3}, [%4];" \
        : "=r"((d)[0]), "=r"((d)[1]), "=r"((d)[2]), "=r"((d)[3]) : "r"(addr))

#define CPASYNC16(dst, src) \
    asm volatile("cp.async.cg.shared.global [%0], [%1], 16;" :: "r"(dst), "l"(src) : "memory")
#define CPASYNC_COMMIT() asm volatile("cp.async.commit_group;" ::: "memory")
#define CPASYNC_WAIT0()  asm volatile("cp.async.wait_group 0;" ::: "memory")
#define CPASYNC_WAIT1()  asm volatile("cp.async.wait_group 1;" ::: "memory")

// =================== small GEMM: Yt = tf32_round((Z @ W)^T) ===================
// W-amortized: 256 CTAs x 128 threads, 128 rows per CTA in 4 chunks of 32.
// W staged ONCE per CTA; Zin streams via 2-buffer cp.async ring.
// Per-row math identical to previous rounds (bit-identical output).
__global__ __launch_bounds__(128) void zw_t_kernel(const float* __restrict__ Z,
                                                   const float* __restrict__ Wp,
                                                   float* __restrict__ Yt) {
    __shared__ float Ws[64 * 68];       // weights, 16B-aligned rows (17 KB)
    __shared__ float Zin[2][32 * 68];   // input ring (17 KB)
    __shared__ float Zout[64 * 33];     // transposed tf32-rounded staging (8.4 KB)
    const int tid = threadIdx.x;
    const int r0 = blockIdx.x * 128;    // 128 consecutive rows (never straddles a batch)
    const int batch = r0 >> 13;
    const int k0 = r0 & (N_ - 1);

    // stage W once: 8 x float4 per thread
    const float4* W4 = reinterpret_cast<const float4*>(Wp);
    #pragma unroll
    for (int i = tid; i < 1024; i += 128) {
        float4 v = W4[i];
        int rr = i >> 4, cc = (i & 15) << 2;
        float* p = &Ws[rr * 68 + cc];
        p[0] = v.x; p[1] = v.y; p[2] = v.z; p[3] = v.w;
    }

    auto LOADZ = [&](int c) {   // 32 rows x 64 floats via cp.async (4 x 16B per thread)
        const uint32_t dstb = s2u(&Zin[c & 1][0]);
        const float* src = Z + (size_t)(r0 + 32 * c) * 64;
        #pragma unroll
        for (int j = 0; j < 4; j++) {
            int idx = tid + (j << 7);          // 0..511
            int rr = idx >> 4, cc = (idx & 15) << 2;
            CPASYNC16(dstb + (uint32_t)(rr * 68 + cc) * 4, src + (idx << 2));
        }
        CPASYNC_COMMIT();
    };
    LOADZ(0);

    const int r = tid >> 2;            // 0..31
    const int g0 = (tid & 3) << 4;     // 0,16,32,48
    const int fo = tid >> 1, kc = (tid & 1) << 4;

    for (int c = 0; c < 4; c++) {
        CPASYNC_WAIT0();
        __syncthreads();   // Zin[c&1] ready; prior Zout store fully consumed; W staged (c==0)

        const float* Zi = &Zin[c & 1][0];
        float4 a0 = make_float4(0.f, 0.f, 0.f, 0.f), a1 = a0, a2 = a0, a3 = a0;
        #pragma unroll 16
        for (int f = 0; f < 64; f++) {
            float zv = Zi[r * 68 + f];
            const float4* wr = reinterpret_cast<const float4*>(&Ws[f * 68 + g0]);
            float4 w0 = wr[0], w1 = wr[1], w2 = wr[2], w3 = wr[3];
            a0.x = fmaf(zv, w0.x, a0.x); a0.y = fmaf(zv, w0.y, a0.y);
            a0.z = fmaf(zv, w0.z, a0.z); a0.w = fmaf(zv, w0.w, a0.w);
            a1.x = fmaf(zv, w1.x, a1.x); a1.y = fmaf(zv, w1.y, a1.y);
            a1.z = fmaf(zv, w1.z, a1.z); a1.w = fmaf(zv, w1.w, a1.w);
            a2.x = fmaf(zv, w2.x, a2.x); a2.y = fmaf(zv, w2.y, a2.y);
            a2.z = fmaf(zv, w2.z, a2.z); a2.w = fmaf(zv, w2.w, a2.w);
            a3.x = fmaf(zv, w3.x, a3.x); a3.y = fmaf(zv, w3.y, a3.y);
            a3.z = fmaf(zv, w3.z, a3.z); a3.w = fmaf(zv, w3.w, a3.w);
        }
        if (c + 1 < 4) LOADZ(c + 1);   // overlap next chunk load with staging/store

        float av[16] = {a0.x, a0.y, a0.z, a0.w, a1.x, a1.y, a1.z, a1.w,
                        a2.x, a2.y, a2.z, a2.w, a3.x, a3.y, a3.z, a3.w};
        #pragma unroll
        for (int j = 0; j < 16; j++)
            Zout[(g0 + j) * 33 + r] = __uint_as_float(tf32r(av[j]));
        __syncthreads();   // Zout complete

        float* dst = Yt + (size_t)(batch * 64 + fo) * N_ + k0 + 32 * c + kc;
        const float* srcp = &Zout[fo * 33 + kc];
        #pragma unroll
        for (int j = 0; j < 16; j += 4)
            *reinterpret_cast<float4*>(dst + j) =
                make_float4(srcp[j], srcp[j + 1], srcp[j + 2], srcp[j + 3]);
    }
}

// =================== big GEMM: part[sk] = A[:, ks] @ Yt[:, ks]^T ===================
// CTA 128M x 128N x (K/2), 128 threads, 4 warps 2x2, warp tile 64x64, split-K=2.
// 3-stage cp.async pipeline for BOTH operands; A rounded to tf32 post-ldmatrix.
#define NT 128                 // k-tiles per CTA (4096 / 32)
#define STAGE_B 16384          // bytes per operand tile
#define SMEM_BYTES (6 * STAGE_B)

__global__ __launch_bounds__(128, 2) void gcn_mma_kernel(const float* __restrict__ A,
                                                         const float* __restrict__ Yt,
                                                         float* __restrict__ part) {
    extern __shared__ float sm[];
    const uint32_t sbase = s2u(sm);
    const int tid = threadIdx.x, lane = tid & 31, wid = tid >> 5;
    const int wm = wid & 1, wn = wid >> 1;
    const int n0 = blockIdx.x << 7;
    const int m0 = blockIdx.y << 7;
    const int kb = blockIdx.z << 12;

    // ldmatrix per-lane geometry
    const int r = lane & 7;
    const int amod = (((lane >> 3) & 1) << 3) + r;
    const int acoff = lane >> 4;
    const int bmod = (((lane >> 4) & 1) << 3) + r;
    const int bcoff = (lane >> 3) & 1;
    const uint32_t aRowB = (uint32_t)(wm * 64 + amod) * 128;
    const uint32_t bRowB = (uint32_t)(wn * 64 + bmod) * 128;

    // staging geometry: thread covers rows (tid>>3)+16j, 16B chunk tid&7
    const int srow = tid >> 3;
    const uint32_t stOff = (uint32_t)srow * 128 + (uint32_t)(((tid & 7) ^ (srow & 7)) << 4);

    const float* gA0 = A + (size_t)(m0 + srow) * N_ + kb + ((tid & 7) << 2);
    const float* gB0 = Yt + (size_t)(n0 + srow) * N_ + kb + ((tid & 7) << 2);

    float acc[4][8][4];
    #pragma unroll
    for (int i = 0; i < 4; i++)
        #pragma unroll
        for (int j = 0; j < 8; j++)
            #pragma unroll
            for (int c = 0; c < 4; c++) acc[i][j][c] = 0.f;

    auto ISSUE = [&](int t) {
        const uint32_t stg = (uint32_t)(t % 3) * STAGE_B;
        const float* gA = gA0 + (size_t)t * 32;
        const float* gB = gB0 + (size_t)t * 32;
        #pragma unroll
        for (int j = 0; j < 8; j++)
            CPASYNC16(sbase + stg + stOff + (uint32_t)j * 2048, gA + (size_t)j * (16 * N_));
        #pragma unroll
        for (int j = 0; j < 8; j++)
            CPASYNC16(sbase + 3 * STAGE_B + stg + stOff + (uint32_t)j * 2048,
                      gB + (size_t)j * (16 * N_));
        CPASYNC_COMMIT();
    };
    ISSUE(0);
    ISSUE(1);

    for (int t = 0; t < NT; t++) {
        const uint32_t stg = (uint32_t)(t % 3) * STAGE_B;
        const uint32_t sa = sbase + stg;
        const uint32_t sb = sbase + 3 * STAGE_B + stg;

        if (t + 1 < NT) { CPASYNC_WAIT1(); } else { CPASYNC_WAIT0(); }
        __syncthreads();

        if (t + 2 < NT) ISSUE(t + 2);   // overlap next-next tile with compute

        // ---- compute 4 k8-steps; A rounded to tf32 in registers
        #pragma unroll
        for (int s = 0; s < 4; s++) {
            uint32_t af[4][4];
            #pragma unroll
            for (int f = 0; f < 4; f++) {
                LDMX4(af[f], sa + aRowB + (uint32_t)f * 2048 +
                             (uint32_t)(((2 * s + acoff) ^ r) << 4));
                af[f][0] = tf32ru(af[f][0]); af[f][1] = tf32ru(af[f][1]);
                af[f][2] = tf32ru(af[f][2]); af[f][3] = tf32ru(af[f][3]);
            }
            uint32_t bq[4][4];
            #pragma unroll
            for (int p = 0; p < 4; p++)
                LDMX4(bq[p], sb + bRowB + (uint32_t)p * 2048 +
                             (uint32_t)(((2 * s + bcoff) ^ r) << 4));
            #pragma unroll
            for (int i = 0; i < 4; i++)
                #pragma unroll
                for (int j = 0; j < 8; j++)
                    MMA_TF32(acc[i][j], af[i], &bq[j >> 1][(j & 1) * 2]);
        }
        __syncthreads();
    }

    // ---- epilogue: store split-K partials
    float* dstb = part + ((size_t)blockIdx.z << 21);
    #pragma unroll
    for (int i = 0; i < 4; i++) {
        int mrow = m0 + wm * 64 + i * 16 + (lane >> 2);
        #pragma unroll
        for (int j = 0; j < 8; j++) {
            int ncol = n0 + wn * 64 + j * 8 + ((lane & 3) << 1);
            float* d0 = dstb + (size_t)mrow * 256 + ncol;
            *reinterpret_cast<float2*>(d0) = make_float2(acc[i][j][0], acc[i][j][1]);
            *reinterpret_cast<float2*>(d0 + 8 * 256) = make_float2(acc[i][j][2], acc[i][j][3]);
        }
    }
}

// =================== reduce 2 split-K partials + relu, scatter to [B,N,F] ===================
// 2 coalesced float4 per thread for better MLP.
__global__ __launch_bounds__(256) void reduce_relu_kernel(const float* __restrict__ part,
                                                          float* __restrict__ out) {
    const float4* p = reinterpret_cast<const float4*>(part);
    #pragma unroll
    for (int pass = 0; pass < 2; pass++) {
        const int idx = blockIdx.x * 512 + pass * 256 + threadIdx.x;
        float4 a = p[idx], b = p[idx + 524288];
        float4 rr;
        rr.x = fmaxf(a.x + b.x, 0.f);
        rr.y = fmaxf(a.y + b.y, 0.f);
        rr.z = fmaxf(a.z + b.z, 0.f);
        rr.w = fmaxf(a.w + b.w, 0.f);
        const int m = idx >> 6;
        const int n = (idx & 63) << 2;
        const int bt = n >> 6, f = n & 63;
        *reinterpret_cast<float4*>(out + ((size_t)bt << 19) + (size_t)m * 64 + f) = rr;
    }
}

// =================== launch ===================
// inputs: 0=x [B,N,F] f32, 1=t (ignored), 2=net_params [2*64*64] f32, 3=A [N,N] f32
extern "C" void kernel_launch(void* const* d_in, const int* in_sizes, int n_in,
                              void* d_out, int out_size) {
    const float* x   = (const float*)d_in[0];
    const float* net = (const float*)d_in[2];
    const float* A   = (const float*)d_in[3];
    float* out = (float*)d_out;

    float *yt, *z, *part;
    cudaGetSymbolAddress((void**)&yt, g_yt);
    cudaGetSymbolAddress((void**)&z, g_z);
    cudaGetSymbolAddress((void**)&part, g_part);

    cudaFuncSetAttribute(gcn_mma_kernel, cudaFuncAttributeMaxDynamicSharedMemorySize,
                         SMEM_BYTES);

    dim3 gmm(2, 64, 2);
    // layer 0: z = relu(A @ (x @ W0))
    zw_t_kernel<<<256, 128>>>(x, net, yt);
    gcn_mma_kernel<<<gmm, 128, SMEM_BYTES>>>(A, yt, part);
    reduce_relu_kernel<<<1024, 256>>>(part, z);
    // layer 1: out = relu(A @ (z @ W1))
    zw_t_kernel<<<256, 128>>>(z, net + F_ * F_, yt);
    gcn_mma_kernel<<<gmm, 128, SMEM_BYTES>>>(A, yt, part);
    reduce_relu_kernel<<<1024, 256>>>(part, out);
}

// round 17
// speedup vs baseline: 1.1446x; 1.1446x over previous
#include <cuda_runtime.h>
#include <cstdint>

#define B_ 4
#define N_ 8192
#define F_ 64

// ---- scratch (__device__ globals; allocation-free rule) ----
__device__ float g_yt[256 * N_];      // (Z@W)^T tf32-rounded, [n=b*64+f][k], 8 MB
__device__ float g_z[B_ * N_ * F_];   // layer-1 activations, 8 MB
__device__ float g_part[2 * N_ * 256];// split-K partials, 16 MB

// =================== helpers ===================
__device__ __forceinline__ uint32_t s2u(const void* p) {
    uint32_t a;
    asm("{ .reg .u64 t; cvta.to.shared.u64 t, %1; cvt.u32.u64 %0, t; }" : "=r"(a) : "l"(p));
    return a;
}
__device__ __forceinline__ uint32_t tf32r(float x) {  // round-to-nearest tf32 (sm_80+)
    uint32_t u;
    asm("cvt.rna.tf32.f32 %0, %1;" : "=r"(u) : "f"(x));
    return u;
}
__device__ __forceinline__ uint32_t tf32ru(uint32_t x) {
    uint32_t u;
    asm("cvt.rna.tf32.f32 %0, %1;" : "=r"(u) : "f"(__uint_as_float(x)));
    return u;
}

#define MMA_TF32(d, a, b) \
    asm volatile( \
        "mma.sync.aligned.m16n8k8.row.col.f32.tf32.tf32.f32 " \
        "{%0,%1,%2,%3}, {%4,%5,%6,%7}, {%8,%9}, {%0,%1,%2,%3};" \
        : "+f"((d)[0]), "+f"((d)[1]), "+f"((d)[2]), "+f"((d)[3]) \
        : "r"((a)[0]), "r"((a)[1]), "r"((a)[2]), "r"((a)[3]), \
          "r"((b)[0]), "r"((b)[1]))

#define LDMX4(d, addr) \
    asm volatile("ldmatrix.sync.aligned.m8n8.x4.shared.b16 {%0,%1,%2,%3}, [%4];" \
        : "=r"((d)[0]), "=r"((d)[1]), "=r"((d)[2]), "=r"((d)[3]) : "r"(addr))

#define CPASYNC16(dst, src) \
    asm volatile("cp.async.cg.shared.global [%0], [%1], 16;" :: "r"(dst), "l"(src) : "memory")
#define CPASYNC_COMMIT() asm volatile("cp.async.commit_group;" ::: "memory")
#define CPASYNC_WAIT0()  asm volatile("cp.async.wait_group 0;" ::: "memory")
#define CPASYNC_WAIT1()  asm volatile("cp.async.wait_group 1;" ::: "memory")

// =================== zw via tensor cores: Yt = tf32_round((Z @ W)^T) ===================
// Z: [32768, 64] row-major. W: [64, 64]. Yt[n = batch*64+g][k = row-in-batch].
// 256 CTAs x 256 threads. CTA tile: 128 rows x 64 cols. Warp w: m16 rows, n64.
// smem: [0,16K) Wt (transposed, tf32-rounded), [16K,48K) Z tile; Dt aliases after compute.
#define ZW_SMEM 49152

__global__ __launch_bounds__(256) void zw_mma_kernel(const float* __restrict__ Z,
                                                     const float* __restrict__ Wp,
                                                     float* __restrict__ Yt) {
    extern __shared__ float zsm[];
    const uint32_t sW = s2u(zsm);
    const uint32_t sZ = sW + 16384;
    const int tid = threadIdx.x, lane = tid & 31, w = tid >> 5;
    const int r0 = blockIdx.x << 7;           // 128 rows, never straddles a batch
    const int batch = r0 >> 13;
    const int k0 = r0 & (N_ - 1);

    // ---- issue Z tile cp.async: 2048 chunks of 16B, swizzled (chunk ^ (row&7))
    {
        const float* src = Z + (size_t)r0 * 64;
        #pragma unroll
        for (int j = 0; j < 8; j++) {
            int row = (tid >> 4) + (j << 4);  // 0..127
            int c = tid & 15;                 // 16B chunk in row
            uint32_t dst = sZ + (uint32_t)(row * 256 + ((c ^ (row & 7)) << 4));
            CPASYNC16(dst, src + row * 64 + (c << 2));
        }
        CPASYNC_COMMIT();
    }
    // ---- stage W transposed + tf32-rounded: Wt[g][f], same swizzle
    {
        const float4* W4 = reinterpret_cast<const float4*>(Wp);
        #pragma unroll
        for (int i = tid; i < 1024; i += 256) {
            float4 v = W4[i];
            int f = i >> 4, gc = (i & 15) << 2;
            float vs[4] = {v.x, v.y, v.z, v.w};
            #pragma unroll
            for (int l = 0; l < 4; l++) {
                int g = gc + l;
                uint32_t adr = sW + (uint32_t)(g * 256 + (((f >> 2) ^ (g & 7)) << 4) + ((f & 3) << 2));
                asm volatile("st.shared.b32 [%0], %1;" :: "r"(adr), "r"(tf32r(vs[l])) : "memory");
            }
        }
    }
    CPASYNC_WAIT0();
    __syncthreads();

    // ---- fragment geometry (identical to proven R7 pattern, 256B rows)
    const int r = lane & 7;
    const int amod = (((lane >> 3) & 1) << 3) + r;
    const int acoff = lane >> 4;
    const int bmod = (((lane >> 4) & 1) << 3) + r;
    const int bcoff = (lane >> 3) & 1;
    const uint32_t aBase = sZ + (uint32_t)((w * 16 + amod) * 256);
    uint32_t bBase[4];
    #pragma unroll
    for (int p = 0; p < 4; p++) bBase[p] = sW + (uint32_t)((p * 16 + bmod) * 256);

    float acc[8][4];
    #pragma unroll
    for (int j = 0; j < 8; j++)
        #pragma unroll
        for (int c = 0; c < 4; c++) acc[j][c] = 0.f;

    #pragma unroll
    for (int s = 0; s < 8; s++) {
        uint32_t af[4];
        LDMX4(af, aBase + (uint32_t)(((2 * s + acoff) ^ r) << 4));
        af[0] = tf32ru(af[0]); af[1] = tf32ru(af[1]);
        af[2] = tf32ru(af[2]); af[3] = tf32ru(af[3]);
        uint32_t bq[4][4];
        #pragma unroll
        for (int p = 0; p < 4; p++)
            LDMX4(bq[p], bBase[p] + (uint32_t)(((2 * s + bcoff) ^ r) << 4));
        #pragma unroll
        for (int j = 0; j < 8; j++)
            MMA_TF32(acc[j], af, &bq[j >> 1][(j & 1) * 2]);
    }
    __syncthreads();   // done reading Wt/Z; alias Dt over them

    // ---- epilogue: transpose through smem (Dt[n][m], stride 132 for f4 alignment)
    float* Dt = zsm;
    {
        const int m0w = w * 16 + (lane >> 2);
        const int nb = (lane & 3) << 1;
        #pragma unroll
        for (int j = 0; j < 8; j++) {
            int n = j * 8 + nb;
            Dt[n * 132 + m0w]             = acc[j][0];
            Dt[(n + 1) * 132 + m0w]       = acc[j][1];
            Dt[n * 132 + m0w + 8]         = acc[j][2];
            Dt[(n + 1) * 132 + m0w + 8]   = acc[j][3];
        }
    }
    __syncthreads();

    // ---- coalesced tf32-rounded store: thread t -> n = t>>2, m-chunk (t&3)*32
    {
        const int n = tid >> 2, mc = (tid & 3) << 5;
        float* dst = Yt + (size_t)(batch * 64 + n) * N_ + k0 + mc;
        const float* srcp = &Dt[n * 132 + mc];
        #pragma unroll
        for (int jj = 0; jj < 32; jj += 4) {
            *reinterpret_cast<float4*>(dst + jj) = make_float4(
                __uint_as_float(tf32r(srcp[jj])),     __uint_as_float(tf32r(srcp[jj + 1])),
                __uint_as_float(tf32r(srcp[jj + 2])), __uint_as_float(tf32r(srcp[jj + 3])));
        }
    }
}

// =================== big GEMM: part[sk] = A[:, ks] @ Yt[:, ks]^T ===================
// CTA 128M x 128N x (K/2), 128 threads, 4 warps 2x2, warp tile 64x64, split-K=2.
// 3-stage cp.async pipeline for BOTH operands; A rounded to tf32 post-ldmatrix.
#define NT 128                 // k-tiles per CTA (4096 / 32)
#define STAGE_B 16384          // bytes per operand tile
#define SMEM_BYTES (6 * STAGE_B)

__global__ __launch_bounds__(128, 2) void gcn_mma_kernel(const float* __restrict__ A,
                                                         const float* __restrict__ Yt,
                                                         float* __restrict__ part) {
    extern __shared__ float sm[];
    const uint32_t sbase = s2u(sm);
    const int tid = threadIdx.x, lane = tid & 31, wid = tid >> 5;
    const int wm = wid & 1, wn = wid >> 1;
    const int n0 = blockIdx.x << 7;
    const int m0 = blockIdx.y << 7;
    const int kb = blockIdx.z << 12;

    // ldmatrix per-lane geometry
    const int r = lane & 7;
    const int amod = (((lane >> 3) & 1) << 3) + r;
    const int acoff = lane >> 4;
    const int bmod = (((lane >> 4) & 1) << 3) + r;
    const int bcoff = (lane >> 3) & 1;
    const uint32_t aRowB = (uint32_t)(wm * 64 + amod) * 128;
    const uint32_t bRowB = (uint32_t)(wn * 64 + bmod) * 128;

    // staging geometry: thread covers rows (tid>>3)+16j, 16B chunk tid&7
    const int srow = tid >> 3;
    const uint32_t stOff = (uint32_t)srow * 128 + (uint32_t)(((tid & 7) ^ (srow & 7)) << 4);

    const float* gA0 = A + (size_t)(m0 + srow) * N_ + kb + ((tid & 7) << 2);
    const float* gB0 = Yt + (size_t)(n0 + srow) * N_ + kb + ((tid & 7) << 2);

    float acc[4][8][4];
    #pragma unroll
    for (int i = 0; i < 4; i++)
        #pragma unroll
        for (int j = 0; j < 8; j++)
            #pragma unroll
            for (int c = 0; c < 4; c++) acc[i][j][c] = 0.f;

    auto ISSUE = [&](int t) {
        const uint32_t stg = (uint32_t)(t % 3) * STAGE_B;
        const float* gA = gA0 + (size_t)t * 32;
        const float* gB = gB0 + (size_t)t * 32;
        #pragma unroll
        for (int j = 0; j < 8; j++)
            CPASYNC16(sbase + stg + stOff + (uint32_t)j * 2048, gA + (size_t)j * (16 * N_));
        #pragma unroll
        for (int j = 0; j < 8; j++)
            CPASYNC16(sbase + 3 * STAGE_B + stg + stOff + (uint32_t)j * 2048,
                      gB + (size_t)j * (16 * N_));
        CPASYNC_COMMIT();
    };
    ISSUE(0);
    ISSUE(1);

    for (int t = 0; t < NT; t++) {
        const uint32_t stg = (uint32_t)(t % 3) * STAGE_B;
        const uint32_t sa = sbase + stg;
        const uint32_t sb = sbase + 3 * STAGE_B + stg;

        if (t + 1 < NT) { CPASYNC_WAIT1(); } else { CPASYNC_WAIT0(); }
        __syncthreads();

        if (t + 2 < NT) ISSUE(t + 2);   // overlap next-next tile with compute

        // ---- compute 4 k8-steps; A rounded to tf32 in registers
        #pragma unroll
        for (int s = 0; s < 4; s++) {
            uint32_t af[4][4];
            #pragma unroll
            for (int f = 0; f < 4; f++) {
                LDMX4(af[f], sa + aRowB + (uint32_t)f * 2048 +
                             (uint32_t)(((2 * s + acoff) ^ r) << 4));
                af[f][0] = tf32ru(af[f][0]); af[f][1] = tf32ru(af[f][1]);
                af[f][2] = tf32ru(af[f][2]); af[f][3] = tf32ru(af[f][3]);
            }
            uint32_t bq[4][4];
            #pragma unroll
            for (int p = 0; p < 4; p++)
                LDMX4(bq[p], sb + bRowB + (uint32_t)p * 2048 +
                             (uint32_t)(((2 * s + bcoff) ^ r) << 4));
            #pragma unroll
            for (int i = 0; i < 4; i++)
                #pragma unroll
                for (int j = 0; j < 8; j++)
                    MMA_TF32(acc[i][j], af[i], &bq[j >> 1][(j & 1) * 2]);
        }
        __syncthreads();
    }

    // ---- epilogue: store split-K partials
    float* dstb = part + ((size_t)blockIdx.z << 21);
    #pragma unroll
    for (int i = 0; i < 4; i++) {
        int mrow = m0 + wm * 64 + i * 16 + (lane >> 2);
        #pragma unroll
        for (int j = 0; j < 8; j++) {
            int ncol = n0 + wn * 64 + j * 8 + ((lane & 3) << 1);
            float* d0 = dstb + (size_t)mrow * 256 + ncol;
            *reinterpret_cast<float2*>(d0) = make_float2(acc[i][j][0], acc[i][j][1]);
            *reinterpret_cast<float2*>(d0 + 8 * 256) = make_float2(acc[i][j][2], acc[i][j][3]);
        }
    }
}

// =================== reduce 2 split-K partials + relu, scatter to [B,N,F] ===================
__global__ __launch_bounds__(256) void reduce_relu_kernel(const float* __restrict__ part,
                                                          float* __restrict__ out) {
    const float4* p = reinterpret_cast<const float4*>(part);
    #pragma unroll
    for (int pass = 0; pass < 2; pass++) {
        const int idx = blockIdx.x * 512 + pass * 256 + threadIdx.x;
        float4 a = p[idx], b = p[idx + 524288];
        float4 rr;
        rr.x = fmaxf(a.x + b.x, 0.f);
        rr.y = fmaxf(a.y + b.y, 0.f);
        rr.z = fmaxf(a.z + b.z, 0.f);
        rr.w = fmaxf(a.w + b.w, 0.f);
        const int m = idx >> 6;
        const int n = (idx & 63) << 2;
        const int bt = n >> 6, f = n & 63;
        *reinterpret_cast<float4*>(out + ((size_t)bt << 19) + (size_t)m * 64 + f) = rr;
    }
}

// =================== launch ===================
// inputs: 0=x [B,N,F] f32, 1=t (ignored), 2=net_params [2*64*64] f32, 3=A [N,N] f32
extern "C" void kernel_launch(void* const* d_in, const int* in_sizes, int n_in,
                              void* d_out, int out_size) {
    const float* x   = (const float*)d_in[0];
    const float* net = (const float*)d_in[2];
    const float* A   = (const float*)d_in[3];
    float* out = (float*)d_out;

    float *yt, *z, *part;
    cudaGetSymbolAddress((void**)&yt, g_yt);
    cudaGetSymbolAddress((void**)&z, g_z);
    cudaGetSymbolAddress((void**)&part, g_part);

    cudaFuncSetAttribute(gcn_mma_kernel, cudaFuncAttributeMaxDynamicSharedMemorySize,
                         SMEM_BYTES);
    cudaFuncSetAttribute(zw_mma_kernel, cudaFuncAttributeMaxDynamicSharedMemorySize,
                         ZW_SMEM);

    dim3 gmm(2, 64, 2);
    // layer 0: z = relu(A @ (x @ W0))
    zw_mma_kernel<<<256, 256, ZW_SMEM>>>(x, net, yt);
    gcn_mma_kernel<<<gmm, 128, SMEM_BYTES>>>(A, yt, part);
    reduce_relu_kernel<<<1024, 256>>>(part, z);
    // layer 1: out = relu(A @ (z @ W1))
    zw_mma_kernel<<<256, 256, ZW_SMEM>>>(z, net + F_ * F_, yt);
    gcn_mma_kernel<<<gmm, 128, SMEM_BYTES>>>(A, yt, part);
    reduce_relu_kernel<<<1024, 256>>>(part, out);
}